// round 17
// baseline (speedup 1.0000x reference)
#include <cuda_runtime.h>
#include <cuda_bf16.h>
#include <cuda_fp16.h>
#include <math.h>
#include <stdint.h>

// Problem constants (fixed for this dataset)
#define NNODES 50000
#define MAXE   262144
#define DDIM   128
#define HDIM   256
#define NEXP   4

// ---------------- device scratch (static allocation only) ----------------
__device__ int   g_counts[NEXP];
__device__ int   g_flag64;
__device__ int   g_bucket[NEXP][MAXE];      // 4 MB
__device__ float g_topv[MAXE];              // 1 MB
__device__ float g_partial[4096][NEXP];     // per gate-block prob sums
// f16x2-packed W1, TRANSPOSED per 64-K chunk: word[chunk][col][kpair 0..31]
__device__ uint32_t g_w1t[131072];

#define OFF2_CAT  0
#define OFF2_DIST 32768
#define OFF2_MUL  49152
#define OFF2_ALL  65536

// ---------------- helpers ----------------
__device__ __forceinline__ void mma_f16(float c[4],
                                        uint32_t a0, uint32_t a1, uint32_t a2, uint32_t a3,
                                        uint32_t b0, uint32_t b1) {
    asm volatile(
        "mma.sync.aligned.m16n8k16.row.col.f32.f16.f16.f32 "
        "{%0,%1,%2,%3}, {%4,%5,%6,%7}, {%8,%9}, {%0,%1,%2,%3};"
        : "+f"(c[0]), "+f"(c[1]), "+f"(c[2]), "+f"(c[3])
        : "r"(a0), "r"(a1), "r"(a2), "r"(a3), "r"(b0), "r"(b1));
}

__device__ __forceinline__ void ldsm_x4(uint32_t& r0, uint32_t& r1,
                                        uint32_t& r2, uint32_t& r3, uint32_t addr) {
    asm volatile("ldmatrix.sync.aligned.m8n8.x4.shared.b16 {%0,%1,%2,%3}, [%4];"
                 : "=r"(r0), "=r"(r1), "=r"(r2), "=r"(r3) : "r"(addr));
}

__device__ __forceinline__ uint32_t packh2(float lo, float hi) {
    const __half2 h = __floats2half2_rn(lo, hi);
    return *reinterpret_cast<const uint32_t*>(&h);
}

__device__ __forceinline__ void cp_async16(uint32_t smem_addr, const void* gptr) {
    asm volatile("cp.async.cg.shared.global [%0], [%1], 16;\n"
                 :: "r"(smem_addr), "l"(gptr));
}
__device__ __forceinline__ void cp_async_commit() {
    asm volatile("cp.async.commit_group;\n");
}
__device__ __forceinline__ void cp_async_wait0() {
    asm volatile("cp.async.wait_group 0;\n");
}

// ---------------- kernel 0: init + index dtype sniff (1 block) --------------
__global__ void k_prep(const void* __restrict__ uptr) {
    if (threadIdx.x < NEXP) g_counts[threadIdx.x] = 0;
    if (threadIdx.x == 0) {
        const int* p = (const int*)uptr;
        int is64 = 1;
        #pragma unroll 1
        for (int i = 0; i < 64; i++) {
            if (p[2 * i + 1] != 0) { is64 = 0; break; }
        }
        g_flag64 = is64;
    }
}

// ---------------- kernel 1: gate (+ distributed W pack in blocks < 512) -----
__global__ __launch_bounds__(256) void k_gate(
    const float* __restrict__ z,
    const void*  __restrict__ u_, const void* __restrict__ v_,
    const float* __restrict__ gate_w,   // [512,4] row-major
    const float* __restrict__ gate_b,   // [4]
    const float* __restrict__ w_cat, const float* __restrict__ w_dist,
    const float* __restrict__ w_mul, const float* __restrict__ w_all,
    int E)
{
    __shared__ __align__(16) float sgw[512 * 4];
    __shared__ float wpart[8][NEXP];
    __shared__ int   sarg[64];
    __shared__ int   srank[64];
    __shared__ int   scnt[NEXP];
    __shared__ int   sbase[NEXP];

    const int tid  = threadIdx.x;
    const int warp = tid >> 5;
    const int lane = tid & 31;

    // ---- distributed W1 pack+transpose (only by k_experts later) ----
    if (blockIdx.x < 512) {
        const int idx = (int)blockIdx.x * 256 + tid;   // [0, 131072)
        const float* src;
        int base;
        if (idx < OFF2_DIST)      { src = w_cat;  base = OFF2_CAT;  }
        else if (idx < OFF2_MUL)  { src = w_dist; base = OFF2_DIST; }
        else if (idx < OFF2_ALL)  { src = w_mul;  base = OFF2_MUL;  }
        else                      { src = w_all;  base = OFF2_ALL;  }
        const int r     = idx - base;
        const int chunk = r >> 13;
        const int rem   = r & 8191;
        const int col   = rem >> 5;
        const int kpl   = rem & 31;
        const int kp    = chunk * 32 + kpl;
        g_w1t[idx] = packh2(src[kp * 512 + col], src[kp * 512 + 256 + col]);
    }

    for (int t = tid; t < 2048; t += 256) sgw[t] = gate_w[t];
    if (tid < NEXP) scnt[tid] = 0;
    __syncthreads();

    const int flag64 = g_flag64;
    const float4* gw4 = reinterpret_cast<const float4*>(sgw);

    const int ebase = (int)blockIdx.x * 64 + warp * 8;
    int uu[8], vv[8];
    #pragma unroll
    for (int t = 0; t < 8; t++) {
        const int e = ebase + t;
        if (e < E) {
            if (flag64) {
                uu[t] = (int)((const long long*)u_)[e];
                vv[t] = (int)((const long long*)v_)[e];
            } else {
                uu[t] = ((const int*)u_)[e];
                vv[t] = ((const int*)v_)[e];
            }
        } else { uu[t] = 0; vv[t] = 0; }
    }

    float p0 = 0.f, p1 = 0.f, p2 = 0.f, p3 = 0.f;

    #pragma unroll 1
    for (int pass = 0; pass < 2; pass++) {
        float za[4][4], zb[4][4];
        #pragma unroll
        for (int e = 0; e < 4; e++) {
            const int t = pass * 4 + e;
            const float* zu = z + (size_t)uu[t] * DDIM;
            const float* zv = z + (size_t)vv[t] * DDIM;
            #pragma unroll
            for (int kk = 0; kk < 4; kk++) {
                za[e][kk] = zu[lane + kk * 32];
                zb[e][kk] = zv[lane + kk * 32];
            }
        }

        float g[4][4];
        #pragma unroll
        for (int e = 0; e < 4; e++)
            #pragma unroll
            for (int j = 0; j < 4; j++) g[e][j] = 0.f;

        #pragma unroll
        for (int kk = 0; kk < 4; kk++) {
            const int k = lane + kk * 32;
            const float4 wA = gw4[k];
            const float4 wB = gw4[128 + k];
            const float4 wD = gw4[256 + k];
            const float4 wM = gw4[384 + k];
            #pragma unroll
            for (int e = 0; e < 4; e++) {
                const float a = za[e][kk];
                const float b = zb[e][kk];
                const float d = fabsf(a - b);
                const float m = a * b;
                g[e][0] += a * wA.x + b * wB.x + d * wD.x + m * wM.x;
                g[e][1] += a * wA.y + b * wB.y + d * wD.y + m * wM.y;
                g[e][2] += a * wA.z + b * wB.z + d * wD.z + m * wM.z;
                g[e][3] += a * wA.w + b * wB.w + d * wD.w + m * wM.w;
            }
        }

        #pragma unroll
        for (int off = 16; off; off >>= 1) {
            #pragma unroll
            for (int e = 0; e < 4; e++) {
                #pragma unroll
                for (int j = 0; j < 4; j++)
                    g[e][j] += __shfl_xor_sync(0xffffffffu, g[e][j], off);
            }
        }

        if (lane < 4) {
            float l[NEXP];
            if (lane == 0)      { l[0] = g[0][0]; l[1] = g[0][1]; l[2] = g[0][2]; l[3] = g[0][3]; }
            else if (lane == 1) { l[0] = g[1][0]; l[1] = g[1][1]; l[2] = g[1][2]; l[3] = g[1][3]; }
            else if (lane == 2) { l[0] = g[2][0]; l[1] = g[2][1]; l[2] = g[2][2]; l[3] = g[2][3]; }
            else                { l[0] = g[3][0]; l[1] = g[3][1]; l[2] = g[3][2]; l[3] = g[3][3]; }

            const int t = pass * 4 + lane;
            const int e = ebase + t;
            if (e < E) {
                #pragma unroll
                for (int j = 0; j < NEXP; j++) l[j] += gate_b[j];
                float mx = l[0];
                #pragma unroll
                for (int j = 1; j < NEXP; j++) mx = fmaxf(mx, l[j]);
                float ex[NEXP]; float s = 0.f;
                #pragma unroll
                for (int j = 0; j < NEXP; j++) { ex[j] = expf(l[j] - mx); s += ex[j]; }
                const float inv = 1.f / s;
                float pr[NEXP];
                #pragma unroll
                for (int j = 0; j < NEXP; j++) pr[j] = ex[j] * inv;
                int arg = 0; float best = pr[0];
                #pragma unroll
                for (int j = 1; j < NEXP; j++) if (pr[j] > best) { best = pr[j]; arg = j; }

                g_topv[e] = best;
                sarg[warp * 8 + t] = arg;
                p0 += pr[0]; p1 += pr[1]; p2 += pr[2]; p3 += pr[3];
            }
        }
    }

    #pragma unroll
    for (int off = 16; off; off >>= 1) {
        p0 += __shfl_xor_sync(0xffffffffu, p0, off);
        p1 += __shfl_xor_sync(0xffffffffu, p1, off);
        p2 += __shfl_xor_sync(0xffffffffu, p2, off);
        p3 += __shfl_xor_sync(0xffffffffu, p3, off);
    }
    if (lane == 0) {
        wpart[warp][0] = p0; wpart[warp][1] = p1;
        wpart[warp][2] = p2; wpart[warp][3] = p3;
    }
    __syncthreads();

    const int e0 = (int)blockIdx.x * 64 + tid;
    if (tid < 64 && e0 < E) {
        srank[tid] = atomicAdd(&scnt[sarg[tid]], 1);
    }
    __syncthreads();
    if (tid < NEXP) {
        sbase[tid] = atomicAdd(&g_counts[tid], scnt[tid]);
        float s = 0.f;
        #pragma unroll
        for (int w = 0; w < 8; w++) s += wpart[w][tid];
        g_partial[blockIdx.x][tid] = s;
    }
    __syncthreads();
    if (tid < 64 && e0 < E) {
        const int a = sarg[tid];
        g_bucket[a][sbase[a] + srank[tid]] = e0;
    }
}

// ---------------- kernel 2: merged experts (ldmatrix A+B, fused aux) --------
// r16 structure; W image pre-transposed per chunk: row = col (36-word stride),
// B fragments via 2 ldmatrix.x4 per k16 step (replaces 8 scalar LDS).
// Last block also computes the aux loss (reuses red[] as scratch).

#define KC      64
#define XROW    36                            // X row stride (32 + 4 pad)
#define WROW    36                            // W row stride (32 + 4 pad)
#define BUFSZ   (64 * XROW + 256 * WROW)      // 2304 + 9216 = 11520 words

__global__ __launch_bounds__(256, 2) void k_experts(
    const float* __restrict__ z,
    const void*  __restrict__ u_, const void* __restrict__ v_,
    const float* __restrict__ cb1, const float* __restrict__ cw2, const float* __restrict__ cb2,
    const float* __restrict__ db1, const float* __restrict__ dw2, const float* __restrict__ db2,
    const float* __restrict__ mb1, const float* __restrict__ mw2, const float* __restrict__ mb2,
    const float* __restrict__ ab1, const float* __restrict__ aw2, const float* __restrict__ ab2,
    float* __restrict__ out, int out_size, int gateBlocks, int E)
{
    extern __shared__ __align__(16) uint32_t sm[];
    float* sb1 = (float*)(sm + 2 * BUFSZ);   // [256]
    float* sw2 = sb1 + 256;                  // [256]
    float* red = sw2 + 256;                  // [64][8]
    float* stv = red + 512;                  // [64]
    int*   se  = (int*)(stv + 64);           // [64]
    int*   su  = se + 64;                    // [64]
    int*   sv  = su + 64;                    // [64]

    const int tid  = threadIdx.x;
    const int warp = tid >> 5;
    const int lane = tid & 31;
    const int lq   = lane & 3;
    const int lg   = lane >> 2;
    const int ed   = tid >> 2;               // X-fill: edge (0..63)
    const int qd   = tid & 3;                // X-fill: 16-dim quarter

    // ldmatrix A lane mapping (canonical x4 -> mma A)
    const int arow = (lane & 7) + ((lane >> 3) & 1) * 8;
    const int akof = (lane >> 4) * 4;        // words
    // ldmatrix B lane mapping: matrix bm (0..3), row br
    const int bm = lane >> 3;
    const int br = lane & 7;
    const int bcol_off = (bm >> 1) * 8 + br; // col within warp's 16-col pair group
    const int bkof     = (bm & 1) * 4;       // word offset (b0 vs b1)

    const int flag64 = g_flag64;

    // ---- fused aux loss (last block only; g_partial ready from k_gate) ----
    if (blockIdx.x == gridDim.x - 1) {
        float* s = red;
        float acc4[NEXP] = {0.f, 0.f, 0.f, 0.f};
        for (int i = tid; i < gateBlocks; i += 256) {
            #pragma unroll
            for (int j = 0; j < NEXP; j++) acc4[j] += g_partial[i][j];
        }
        float tot[NEXP];
        #pragma unroll
        for (int j = 0; j < NEXP; j++) {
            s[tid] = acc4[j];
            __syncthreads();
            for (int st = 128; st; st >>= 1) {
                if (tid < st) s[tid] += s[tid + st];
                __syncthreads();
            }
            tot[j] = s[0];
            __syncthreads();
        }
        if (tid == 0 && out_size > E) {
            float aux = 0.f;
            const float invE = 1.f / (float)E;
            #pragma unroll
            for (int j = 0; j < NEXP; j++) {
                const float m = tot[j] * invE;
                aux += m * m;
            }
            out[E] = aux * (float)NEXP;
        }
        __syncthreads();
    }

    int wgr[8];
    #pragma unroll
    for (int i = 0; i < 8; i++) wgr[i] = tid + i * 256;   // cp.async granules

    const int c0n = g_counts[0], c1n = g_counts[1], c2n = g_counts[2], c3n = g_counts[3];
    const int nt0 = (c0n + 63) >> 6, nt1 = (c1n + 63) >> 6;
    const int nt2 = (c2n + 63) >> 6, nt3 = (c3n + 63) >> 6;
    const int p1 = nt0, p2 = p1 + nt1, p3 = p2 + nt2, total = p3 + nt3;

    for (int t = blockIdx.x; t < total; t += gridDim.x) {
        int ex, tile, K, cnt, woff;
        const float *b1p, *w2p, *b2p;
        if (t < p1)      { ex = 0; tile = t;      K = 256; cnt = c0n; woff = OFF2_CAT;  b1p = cb1; w2p = cw2; b2p = cb2; }
        else if (t < p2) { ex = 1; tile = t - p1; K = 128; cnt = c1n; woff = OFF2_DIST; b1p = db1; w2p = dw2; b2p = db2; }
        else if (t < p3) { ex = 2; tile = t - p2; K = 128; cnt = c2n; woff = OFF2_MUL;  b1p = mb1; w2p = mw2; b2p = mb2; }
        else             { ex = 3; tile = t - p3; K = 512; cnt = c3n; woff = OFF2_ALL;  b1p = ab1; w2p = aw2; b2p = ab2; }
        const uint32_t* w1 = g_w1t + woff;
        const int NCH  = K >> 6;             // KC=64
        const int MODE = ex;

        __syncthreads();   // smem reuse guard across tiles
        if (tid < 256) { sb1[tid] = b1p[tid]; sw2[tid] = w2p[tid]; }
        const float b2s = b2p[0];

        const int base = tile * 64;
        const int nE   = min(64, cnt - base);

        if (tid < 64) {
            int e = (tid < nE) ? g_bucket[ex][base + tid] : -1;
            se[tid]  = e;
            stv[tid] = (e >= 0) ? g_topv[e] : 0.f;
            int uu = 0, vv = 0;
            if (e >= 0) {
                if (flag64) {
                    uu = (int)((const long long*)u_)[e];
                    vv = (int)((const long long*)v_)[e];
                } else {
                    uu = ((const int*)u_)[e];
                    vv = ((const int*)v_)[e];
                }
            }
            su[tid] = uu; sv[tid] = vv;
        }
        __syncthreads();

        const float* zu = z + (size_t)su[ed] * DDIM;
        const float* zv = z + (size_t)sv[ed] * DDIM;

        float acc[4][4][4];
        #pragma unroll
        for (int m = 0; m < 4; m++)
            #pragma unroll
            for (int n = 0; n < 4; n++)
                #pragma unroll
                for (int q = 0; q < 4; q++) acc[m][n][q] = 0.f;

        // X fill (edge-major, identical to r16)
        auto fill_x = [&](uint32_t* bX, int kb) {
            const int type  = kb >> 7;
            const int inner = kb & 127;
            bool useA, useB;
            if (MODE == 0)      { useA = (type == 0); useB = (type == 1); }
            else if (MODE == 3) { useA = (type != 1); useB = (type != 0); }
            else                { useA = true;        useB = true;        }
            uint32_t wout[8];
            #pragma unroll
            for (int h = 0; h < 4; h++) {
                const int d = inner + h * 16 + qd * 4;
                float4 a4 = make_float4(0.f, 0.f, 0.f, 0.f);
                float4 b4 = make_float4(0.f, 0.f, 0.f, 0.f);
                if (useA) a4 = *reinterpret_cast<const float4*>(zu + d);
                if (useB) b4 = *reinterpret_cast<const float4*>(zv + d);
                const float av[4] = { a4.x, a4.y, a4.z, a4.w };
                const float bv[4] = { b4.x, b4.y, b4.z, b4.w };
                float vals[4];
                #pragma unroll
                for (int i = 0; i < 4; i++) {
                    if (MODE == 0)      vals[i] = (type == 0) ? av[i] : bv[i];
                    else if (MODE == 1) vals[i] = fabsf(av[i] - bv[i]);
                    else if (MODE == 2) vals[i] = av[i] * bv[i];
                    else {
                        if (type == 0)      vals[i] = av[i];
                        else if (type == 1) vals[i] = bv[i];
                        else if (type == 2) vals[i] = fabsf(av[i] - bv[i]);
                        else                vals[i] = av[i] * bv[i];
                    }
                }
                wout[h * 2 + 0] = packh2(vals[0], vals[1]);
                wout[h * 2 + 1] = packh2(vals[2], vals[3]);
            }
            uint32_t* rowp = bX + ed * XROW;
            #pragma unroll
            for (int h = 0; h < 4; h++) {
                rowp[h * 8 + qd * 2 + 0] = wout[h * 2 + 0];
                rowp[h * 8 + qd * 2 + 1] = wout[h * 2 + 1];
            }
        };

        // W chunk cp.async: granule g -> row col=g>>3, words (g&7)*4
        auto fill_w = [&](uint32_t* bW, int cb) {
            const uint32_t* wsrc = w1 + (size_t)cb * 8192;
            #pragma unroll
            for (int i = 0; i < 8; i++) {
                const int g = wgr[i];
                const uint32_t dst = (uint32_t)__cvta_generic_to_shared(
                    bW + (g >> 3) * WROW + (g & 7) * 4);
                cp_async16(dst, wsrc + g * 4);
            }
            cp_async_commit();
        };

        // ---- prologue: chunk 0 into buffer 0 ----
        {
            fill_w(sm + 64 * XROW, 0);
            fill_x(sm, 0);
            cp_async_wait0();
        }
        __syncthreads();

        #pragma unroll 1
        for (int cb = 0; cb < NCH; cb++) {
            uint32_t* cur = sm + (cb & 1) * BUFSZ;
            uint32_t* nxt = sm + ((cb + 1) & 1) * BUFSZ;

            const bool more = (cb + 1 < NCH);
            if (more) {
                fill_w(nxt + 64 * XROW, cb + 1);
                fill_x(nxt, (cb + 1) * KC);
            }

            const uint32_t Xb = (uint32_t)__cvta_generic_to_shared(cur);
            const uint32_t Wb = (uint32_t)__cvta_generic_to_shared(cur + 64 * XROW);

            #pragma unroll
            for (int s = 0; s < 4; s++) {        // 4 x k16 steps
                // B fragments: 2 x ldmatrix.x4 (n-tiles 0,1 then 2,3)
                uint32_t bh[4][2];
                const uint32_t baddr0 = Wb +
                    (uint32_t)(((warp * 32 + bcol_off) * WROW + s * 8 + bkof) * 4);
                ldsm_x4(bh[0][0], bh[0][1], bh[1][0], bh[1][1], baddr0);
                ldsm_x4(bh[2][0], bh[2][1], bh[3][0], bh[3][1],
                        baddr0 + (uint32_t)(16 * WROW * 4));

                #pragma unroll
                for (int m = 0; m < 4; m++) {
                    uint32_t a0, a1, a2, a3;
                    const uint32_t aaddr = Xb +
                        (uint32_t)(((m * 16 + arow) * XROW + akof + s * 8) * 4);
                    ldsm_x4(a0, a1, a2, a3, aaddr);
                    #pragma unroll
                    for (int n = 0; n < 4; n++)
                        mma_f16(acc[m][n], a0, a1, a2, a3, bh[n][0], bh[n][1]);
                }
            }

            cp_async_wait0();
            __syncthreads();
        }

        // ---- epilogue: relu + layer-2 dot, reduce ----
        float ep[4][2];
        #pragma unroll
        for (int m = 0; m < 4; m++) { ep[m][0] = 0.f; ep[m][1] = 0.f; }

        #pragma unroll
        for (int n = 0; n < 4; n++) {
            const int c0 = warp * 32 + n * 8 + 2 * lq;
            const float bb0 = sb1[c0],     bb1 = sb1[c0 + 1];
            const float ww0 = sw2[c0],     ww1 = sw2[c0 + 1];
            #pragma unroll
            for (int m = 0; m < 4; m++) {
                ep[m][0] += fmaxf(acc[m][n][0] + bb0, 0.f) * ww0
                          + fmaxf(acc[m][n][1] + bb1, 0.f) * ww1;
                ep[m][1] += fmaxf(acc[m][n][2] + bb0, 0.f) * ww0
                          + fmaxf(acc[m][n][3] + bb1, 0.f) * ww1;
            }
        }
        #pragma unroll
        for (int m = 0; m < 4; m++) {
            #pragma unroll
            for (int off = 1; off <= 2; off <<= 1) {
                ep[m][0] += __shfl_xor_sync(0xffffffffu, ep[m][0], off);
                ep[m][1] += __shfl_xor_sync(0xffffffffu, ep[m][1], off);
            }
        }
        if (lq == 0) {
            #pragma unroll
            for (int m = 0; m < 4; m++) {
                red[(m * 16 + lg) * 8 + warp]     = ep[m][0];
                red[(m * 16 + lg + 8) * 8 + warp] = ep[m][1];
            }
        }
        __syncthreads();

        if (tid < 64 && se[tid] >= 0) {
            float s = 0.f;
            #pragma unroll
            for (int w = 0; w < 8; w++) s += red[tid * 8 + w];
            out[se[tid]] = stv[tid] * (s + b2s);
        }
    }
}

// ---------------- host launcher ----------------
#define EXP_SMEM ((2 * BUFSZ + 256 + 256 + 512 + 64 + 192) * 4)

extern "C" void kernel_launch(void* const* d_in, const int* in_sizes, int n_in,
                              void* d_out, int out_size)
{
    const float* z       = (const float*)d_in[0];
    const void*  u       = d_in[1];
    const void*  v       = d_in[2];
    const float* gate_w  = (const float*)d_in[3];
    const float* gate_b  = (const float*)d_in[4];
    const float* cat_w1  = (const float*)d_in[5];
    const float* cat_b1  = (const float*)d_in[6];
    const float* cat_w2  = (const float*)d_in[7];
    const float* cat_b2  = (const float*)d_in[8];
    const float* dist_w1 = (const float*)d_in[9];
    const float* dist_b1 = (const float*)d_in[10];
    const float* dist_w2 = (const float*)d_in[11];
    const float* dist_b2 = (const float*)d_in[12];
    const float* mul_w1  = (const float*)d_in[13];
    const float* mul_b1  = (const float*)d_in[14];
    const float* mul_w2  = (const float*)d_in[15];
    const float* mul_b2  = (const float*)d_in[16];
    const float* all_w1  = (const float*)d_in[17];
    const float* all_b1  = (const float*)d_in[18];
    const float* all_w2  = (const float*)d_in[19];
    const float* all_b2  = (const float*)d_in[20];
    float* out = (float*)d_out;

    const int E = in_sizes[1];                 // 262144
    const int gateBlocks = (E + 63) / 64;      // 4096

    cudaFuncSetAttribute(k_experts, cudaFuncAttributeMaxDynamicSharedMemorySize, EXP_SMEM);

    k_prep<<<1, 256>>>(u);
    k_gate<<<gateBlocks, 256>>>(z, u, v, gate_w, gate_b,
                                cat_w1, dist_w1, mul_w1, all_w1, E);

    k_experts<<<2048, 256, EXP_SMEM>>>(z, u, v,
        cat_b1, cat_w2, cat_b2,
        dist_b1, dist_w2, dist_b2,
        mul_b1, mul_w2, mul_b2,
        all_b1, all_w2, all_b2,
        out, out_size, gateBlocks, E);
}